// round 1
// baseline (speedup 1.0000x reference)
#include <cuda_runtime.h>
#include <cuda_bf16.h>
#include <cstdint>

// Problem shape (fixed by the dataset): x[4096,4], sv[4096,4] -> out[4096,4096]
#define NB 4096
#define NS 4096
#define NK 4
#define TB 64   // b-rows per block
#define TS 64   // s-cols per block

// Precomputed half-angle trig tables (SoA: [k][row]) in device globals
// (no cudaMalloc allowed).
__device__ float g_xc[NK][NB];
__device__ float g_xs[NK][NB];
__device__ float g_sc[NK][NS];
__device__ float g_ss[NK][NS];

// ---------- packed f32x2 helpers (sm_103a FFMA2/FMUL2 path) ----------
__device__ __forceinline__ uint64_t pk2(float lo, float hi) {
    uint64_t r;
    asm("mov.b64 %0, {%1, %2};" : "=l"(r) : "f"(lo), "f"(hi));
    return r;
}
__device__ __forceinline__ uint64_t mul2(uint64_t a, uint64_t b) {
    uint64_t r;
    asm("mul.rn.f32x2 %0, %1, %2;" : "=l"(r) : "l"(a), "l"(b));
    return r;
}
__device__ __forceinline__ uint64_t fma2(uint64_t a, uint64_t b, uint64_t c) {
    uint64_t r;
    asm("fma.rn.f32x2 %0, %1, %2, %3;" : "=l"(r) : "l"(a), "l"(b), "l"(c));
    return r;
}
__device__ __forceinline__ void upk2(uint64_t v, float& lo, float& hi) {
    asm("mov.b64 {%0, %1}, %2;" : "=f"(lo), "=f"(hi) : "l"(v));
}

// ---------- trig precompute: 2*4096*4 = 32768 sincos ----------
__global__ void qk_trig_kernel(const float* __restrict__ x,
                               const float* __restrict__ sv) {
    int idx = blockIdx.x * blockDim.x + threadIdx.x;
    if (idx >= 2 * NB * NK) return;
    int which = idx >> 14;      // 0 = x, 1 = sv  (16384 elements each)
    int e = idx & (NB * NK - 1);
    int row = e >> 2;
    int k = e & 3;
    float v = (which ? sv[e] : x[e]) * 0.5f;
    float s, c;
    sincosf(v, &s, &c);
    if (which) {
        g_sc[k][row] = c;
        g_ss[k][row] = s;
    } else {
        g_xc[k][row] = c;
        g_xs[k][row] = s;
    }
}

// ---------- main kernel: 64x64 tile per 256-thread block ----------
__global__ __launch_bounds__(256) void qk_main_kernel(float* __restrict__ out) {
    __shared__ __align__(16) float sxc[NK][TB];
    __shared__ __align__(16) float sxs[NK][TB];
    __shared__ __align__(16) float ssc[NK][TS];
    __shared__ __align__(16) float sss[NK][TS];

    const int b0 = blockIdx.y * TB;
    const int s0 = blockIdx.x * TS;
    const int t = threadIdx.x;

    // cooperative fill: 256 threads, 4*64=256 elements per array
    {
        int k = t >> 6;
        int i = t & 63;
        sxc[k][i] = g_xc[k][b0 + i];
        sxs[k][i] = g_xs[k][b0 + i];
        ssc[k][i] = g_sc[k][s0 + i];
        sss[k][i] = g_ss[k][s0 + i];
    }
    __syncthreads();

    const int tx = t & 15;   // s sub-tile (4 cols)
    const int ty = t >> 4;   // b sub-tile (4 rows)
    const int sb = tx * 4;

    // Load support-vector trig as packed pairs (2 col-pairs x 4 k, cos & sin).
    // ssc[k][sb..sb+1] is 8B-aligned (sb even) -> LDS.64, conflict-free.
    uint64_t cp[2][NK], sp[2][NK];
#pragma unroll
    for (int p = 0; p < 2; p++) {
#pragma unroll
        for (int k = 0; k < NK; k++) {
            float2 c = *reinterpret_cast<const float2*>(&ssc[k][sb + 2 * p]);
            float2 s = *reinterpret_cast<const float2*>(&sss[k][sb + 2 * p]);
            cp[p][k] = pk2(c.x, c.y);
            sp[p][k] = pk2(s.x, s.y);
        }
    }

#pragma unroll
    for (int r = 0; r < 4; r++) {
        const int bl = ty * 4 + r;       // local b-row
        uint64_t xc[NK], xs[NK];
#pragma unroll
        for (int k = 0; k < NK; k++) {
            float c = sxc[k][bl];
            float s = sxs[k][bl];
            xc[k] = pk2(c, c);
            xs[k] = pk2(s, s);
        }

        uint64_t acc[2];
#pragma unroll
        for (int p = 0; p < 2; p++) {
            uint64_t a = fma2(xs[0], sp[p][0], mul2(xc[0], cp[p][0]));
#pragma unroll
            for (int k = 1; k < NK; k++) {
                uint64_t tk = fma2(xs[k], sp[p][k], mul2(xc[k], cp[p][k]));
                a = mul2(a, tk);
            }
            acc[p] = a;
        }

        float4 o;
        upk2(acc[0], o.x, o.y);
        upk2(acc[1], o.z, o.w);
        o.x = fabsf(o.x);
        o.y = fabsf(o.y);
        o.z = fabsf(o.z);
        o.w = fabsf(o.w);

        *reinterpret_cast<float4*>(
            &out[(size_t)(b0 + bl) * NS + (s0 + sb)]) = o;
    }
}

extern "C" void kernel_launch(void* const* d_in, const int* in_sizes, int n_in,
                              void* d_out, int out_size) {
    const float* x  = (const float*)d_in[0];
    const float* sv = (const float*)d_in[1];
    float* out = (float*)d_out;

    // Precompute half-angle trig tables (32768 sincos).
    qk_trig_kernel<<<(2 * NB * NK + 255) / 256, 256>>>(x, sv);

    // Main tiled kernel: 64x64 grid of 64x64 tiles.
    dim3 grid(NS / TS, NB / TB);
    qk_main_kernel<<<grid, 256>>>(out);
}

// round 2
// speedup vs baseline: 1.0131x; 1.0131x over previous
#include <cuda_runtime.h>
#include <cuda_bf16.h>
#include <cstdint>

// out[b,s] = | prod_k cos((x[b,k]-sv[s,k])/2) |
// cos((a-b)/2) = cos(a/2)cos(b/2) + sin(a/2)sin(b/2)
// Packed f32x2 over k-pairs: one LDS.128 delivers (v0,v1,v2,v3) = two packed operands.
#define NB 4096
#define NS 4096

// ---------- packed f32x2 helpers ----------
__device__ __forceinline__ uint64_t pk2(float lo, float hi) {
    uint64_t r; asm("mov.b64 %0, {%1, %2};" : "=l"(r) : "f"(lo), "f"(hi)); return r;
}
__device__ __forceinline__ void upk2(uint64_t v, float& lo, float& hi) {
    asm("mov.b64 {%0, %1}, %2;" : "=f"(lo), "=f"(hi) : "l"(v));
}
__device__ __forceinline__ uint64_t mul2(uint64_t a, uint64_t b) {
    uint64_t r; asm("mul.rn.f32x2 %0, %1, %2;" : "=l"(r) : "l"(a), "l"(b)); return r;
}
__device__ __forceinline__ uint64_t fma2(uint64_t a, uint64_t b, uint64_t c) {
    uint64_t r; asm("fma.rn.f32x2 %0, %1, %2, %3;" : "=l"(r) : "l"(a), "l"(b), "l"(c)); return r;
}
__device__ __forceinline__ uint64_t abs2(uint64_t v) {
    asm("and.b64 %0, %0, 0x7FFFFFFF7FFFFFFF;" : "+l"(v)); return v;
}

// One fused kernel: per 64x64 output tile, compute the 128 needed half-angle
// sincos pairs in-block (2 __sincosf per thread), then the tile.
__global__ __launch_bounds__(256) void qk_fused_kernel(
    const float* __restrict__ x,
    const float* __restrict__ sv,
    float* __restrict__ out)
{
    // Trig tables, [row][k] float4 layout so LDS.128 gives natural k-pairs.
    __shared__ __align__(16) float sxc[256];  // cos(x/2): row*4+k
    __shared__ __align__(16) float sxs[256];  // sin(x/2)
    __shared__ __align__(16) float ssc[256];  // cos(sv/2), col-transposed slots
    __shared__ __align__(16) float sss[256];  // sin(sv/2)

    const int b0 = blockIdx.y << 6;
    const int s0 = blockIdx.x << 6;
    const int t  = threadIdx.x;

    // ---- fused trig fill: coalesced loads, 2 sincos per thread ----
    {
        const int row = t >> 2;       // 0..63
        const int k   = t & 3;
        float sn, cs;
        float xv = x[b0 * 4 + t];     // == x[(b0+row)*4 + k], coalesced
        __sincosf(xv * 0.5f, &sn, &cs);
        sxc[t] = cs;                  // natural [row][k]
        sxs[t] = sn;

        float vv = sv[s0 * 4 + t];
        __sincosf(vv * 0.5f, &sn, &cs);
        // slot(col) = (col>>2) + 16*(col&3): thread's 4 cols land lane-contiguous
        // (slots tx + 16j), making the per-j LDS.128 conflict-free.
        const int slot = ((row >> 2) + ((row & 3) << 4)) * 4 + k;
        ssc[slot] = cs;
        sss[slot] = sn;
    }
    __syncthreads();

    const int tx = t & 15;            // column group: cols 4*tx .. 4*tx+3
    const int ty = t >> 4;            // row group:    rows 4*ty .. 4*ty+3

    // Hoist the 4 support columns (packed k-pairs), 8 LDS.128 total.
    uint64_t sc01[4], sc23[4], ss01[4], ss23[4];
#pragma unroll
    for (int j = 0; j < 4; j++) {
        ulonglong2 c = *reinterpret_cast<const ulonglong2*>(&ssc[(tx + 16 * j) * 4]);
        ulonglong2 s = *reinterpret_cast<const ulonglong2*>(&sss[(tx + 16 * j) * 4]);
        sc01[j] = c.x; sc23[j] = c.y;
        ss01[j] = s.x; ss23[j] = s.y;
    }

    float* orow = out + (size_t)(b0 + (ty << 2)) * NS + (s0 + (tx << 2));

#pragma unroll
    for (int r = 0; r < 4; r++) {
        ulonglong2 xc = *reinterpret_cast<const ulonglong2*>(&sxc[((ty << 2) + r) * 4]);
        ulonglong2 xs = *reinterpret_cast<const ulonglong2*>(&sxs[((ty << 2) + r) * 4]);

        uint64_t p[4];
#pragma unroll
        for (int j = 0; j < 4; j++) {
            // t01 = (cos d0, cos d1), t23 = (cos d2, cos d3), packed over k
            uint64_t t01 = fma2(xs.x, ss01[j], mul2(xc.x, sc01[j]));
            uint64_t t23 = fma2(xs.y, ss23[j], mul2(xc.y, sc23[j]));
            p[j] = mul2(t01, t23);   // (t0*t2, t1*t3)
        }

        // Cross-combine column pairs: out_j = p[j].lo * p[j].hi, two at a time.
        float p0l, p0h, p1l, p1h, p2l, p2h, p3l, p3h;
        upk2(p[0], p0l, p0h); upk2(p[1], p1l, p1h);
        upk2(p[2], p2l, p2h); upk2(p[3], p3l, p3h);
        uint64_t r01 = abs2(mul2(pk2(p0l, p1l), pk2(p0h, p1h)));  // (out0, out1)
        uint64_t r23 = abs2(mul2(pk2(p2l, p3l), pk2(p2h, p3h)));  // (out2, out3)

        ulonglong2 o; o.x = r01; o.y = r23;
        *reinterpret_cast<ulonglong2*>(orow + (size_t)r * NS) = o;  // STG.128
    }
}

extern "C" void kernel_launch(void* const* d_in, const int* in_sizes, int n_in,
                              void* d_out, int out_size) {
    const float* x  = (const float*)d_in[0];
    const float* sv = (const float*)d_in[1];
    float* out = (float*)d_out;

    dim3 grid(NS / 64, NB / 64);   // 64 x 64 blocks of 64x64 tiles
    qk_fused_kernel<<<grid, 256>>>(x, sv, out);
}